// round 2
// baseline (speedup 1.0000x reference)
#include <cuda_runtime.h>

#define HID  256
#define QN   200
#define NPIX (256 * 256)
#define NB   4

// Scratch for mask_embed (B, Q, C) — __device__ global, allocation-free.
__device__ float g_me[NB * QN * HID];

// ---------------------------------------------------------------------------
// Kernel 1: per-query MLP.  h = relu(q @ w1^T + b1); me = h @ w2^T + b2
// Block: one (batch, 8-query tile). 256 threads: thread t = output channel t.
// ---------------------------------------------------------------------------
__global__ __launch_bounds__(256) void mlp_kernel(
    const float* __restrict__ queries,
    const float* __restrict__ w1, const float* __restrict__ b1,
    const float* __restrict__ w2, const float* __restrict__ b2)
{
    const int b  = blockIdx.y;
    const int q0 = blockIdx.x * 8;
    const int tid = threadIdx.x;

    __shared__ float qs[8][HID];
    __shared__ float hs[8][HID];

    // Load 8 query rows (contiguous 8*256 floats), coalesced.
    const float* qbase = queries + (size_t)(b * QN + q0) * HID;
    for (int i = tid; i < 8 * HID; i += 256)
        qs[i >> 8][i & 255] = qbase[i];
    __syncthreads();

    // Layer 1: thread d computes h[j][d] for 8 queries.
    {
        const int d = tid;
        float acc[8] = {0.f, 0.f, 0.f, 0.f, 0.f, 0.f, 0.f, 0.f};
        const float4* wr = reinterpret_cast<const float4*>(w1 + (size_t)d * HID);
        #pragma unroll 8
        for (int c4 = 0; c4 < HID / 4; c4++) {
            float4 w = wr[c4];
            #pragma unroll
            for (int j = 0; j < 8; j++) {
                acc[j] = fmaf(qs[j][4 * c4 + 0], w.x, acc[j]);
                acc[j] = fmaf(qs[j][4 * c4 + 1], w.y, acc[j]);
                acc[j] = fmaf(qs[j][4 * c4 + 2], w.z, acc[j]);
                acc[j] = fmaf(qs[j][4 * c4 + 3], w.w, acc[j]);
            }
        }
        const float bb = b1[d];
        #pragma unroll
        for (int j = 0; j < 8; j++) {
            float v = acc[j] + bb;
            hs[j][d] = v > 0.f ? v : 0.f;
        }
    }
    __syncthreads();

    // Layer 2: thread c computes me[j][c].
    {
        const int c = tid;
        float acc[8] = {0.f, 0.f, 0.f, 0.f, 0.f, 0.f, 0.f, 0.f};
        const float4* wr = reinterpret_cast<const float4*>(w2 + (size_t)c * HID);
        #pragma unroll 8
        for (int d4 = 0; d4 < HID / 4; d4++) {
            float4 w = wr[d4];
            #pragma unroll
            for (int j = 0; j < 8; j++) {
                acc[j] = fmaf(hs[j][4 * d4 + 0], w.x, acc[j]);
                acc[j] = fmaf(hs[j][4 * d4 + 1], w.y, acc[j]);
                acc[j] = fmaf(hs[j][4 * d4 + 2], w.z, acc[j]);
                acc[j] = fmaf(hs[j][4 * d4 + 3], w.w, acc[j]);
            }
        }
        const float bb = b2[c];
        #pragma unroll
        for (int j = 0; j < 8; j++)
            g_me[(size_t)(b * QN + q0 + j) * HID + c] = acc[j] + bb;   // coalesced in c
    }
}

// ---------------------------------------------------------------------------
// Kernel 2: pred[b,q,p] = sum_c me[b,q,c] * mf[b,c,p]
// Per batch: (200 x 256) @ (256 x 65536).
// Tiling: BQ=40 (200=5*40 exact), BP=128 (65536=512*128 exact).
// A tile (40 x 256, transposed) fully resident in smem (40 KB).
// B streamed in BK=16 slabs (8 KB). 160 threads, 8q x 4p register tile.
// Inner step: 3x LDS.128 -> 32 FFMA  (FMA-bound by design).
// ---------------------------------------------------------------------------
#define BQ 40
#define BP 128
#define BK 16
#define NT 160

__global__ __launch_bounds__(NT) void mask_gemm_kernel(
    const float* __restrict__ mf, float* __restrict__ out)
{
    const int b  = blockIdx.z;
    const int q0 = blockIdx.y * BQ;
    const int p0 = blockIdx.x * BP;

    const float* mfb  = mf  + (size_t)b * HID * NPIX;
    float*       outb = out + (size_t)b * QN  * NPIX;

    __shared__ float sA[HID][BQ];   // me tile, transposed: sA[k][q]  (40 KB)
    __shared__ float sB[BK][BP];    // mf slab                       (8 KB)

    const int tid = threadIdx.x;

    // Load full A tile once (2560 float4, 16 per thread), transpose into sA.
    for (int i = tid; i < BQ * (HID / 4); i += NT) {
        const int qq = i / (HID / 4);
        const int k4 = i % (HID / 4);
        float4 v = reinterpret_cast<const float4*>(
            g_me + (size_t)(b * QN + q0 + qq) * HID)[k4];
        sA[4 * k4 + 0][qq] = v.x;
        sA[4 * k4 + 1][qq] = v.y;
        sA[4 * k4 + 2][qq] = v.z;
        sA[4 * k4 + 3][qq] = v.w;
    }

    const int pg = tid & 31;   // 32 groups of 4 pixels
    const int qg = tid >> 5;   // 5 groups of 8 queries

    float acc[8][4];
    #pragma unroll
    for (int j = 0; j < 8; j++)
        #pragma unroll
        for (int p = 0; p < 4; p++) acc[j][p] = 0.f;

    for (int k0 = 0; k0 < HID; k0 += BK) {
        __syncthreads();   // sB reuse guard; first iter also fences sA load
        // Load B slab: BK x BP floats = 512 float4, strided over 160 threads.
        for (int i = tid; i < BK * (BP / 4); i += NT) {
            const int kk = i / (BP / 4);
            const int c4 = i % (BP / 4);
            reinterpret_cast<float4*>(&sB[kk][0])[c4] =
                reinterpret_cast<const float4*>(
                    mfb + (size_t)(k0 + kk) * NPIX + p0)[c4];
        }
        __syncthreads();

        #pragma unroll
        for (int kk = 0; kk < BK; kk++) {
            float4 a0 = *reinterpret_cast<const float4*>(&sA[k0 + kk][qg * 8]);
            float4 a1 = *reinterpret_cast<const float4*>(&sA[k0 + kk][qg * 8 + 4]);
            float4 bv = *reinterpret_cast<const float4*>(&sB[kk][pg * 4]);
            const float av[8] = {a0.x, a0.y, a0.z, a0.w, a1.x, a1.y, a1.z, a1.w};
            const float bw[4] = {bv.x, bv.y, bv.z, bv.w};
            #pragma unroll
            for (int j = 0; j < 8; j++)
                #pragma unroll
                for (int p = 0; p < 4; p++)
                    acc[j][p] = fmaf(av[j], bw[p], acc[j][p]);
        }
    }

    // Coalesced float4 stores: each warp writes 512 contiguous bytes per row.
    #pragma unroll
    for (int j = 0; j < 8; j++) {
        float4 v = make_float4(acc[j][0], acc[j][1], acc[j][2], acc[j][3]);
        reinterpret_cast<float4*>(
            outb + (size_t)(q0 + qg * 8 + j) * NPIX + p0)[pg] = v;
    }
}

// ---------------------------------------------------------------------------
extern "C" void kernel_launch(void* const* d_in, const int* in_sizes, int n_in,
                              void* d_out, int out_size)
{
    const float* queries = (const float*)d_in[0];  // (4, 200, 256)
    const float* mf      = (const float*)d_in[1];  // (4, 256, 256, 256)
    const float* w1      = (const float*)d_in[2];  // (256, 256)
    const float* b1      = (const float*)d_in[3];  // (256,)
    const float* w2      = (const float*)d_in[4];  // (256, 256)
    const float* b2      = (const float*)d_in[5];  // (256,)
    float* out = (float*)d_out;                    // (4, 200, 256, 256)

    mlp_kernel<<<dim3(QN / 8, NB), 256>>>(queries, w1, b1, w2, b2);
    mask_gemm_kernel<<<dim3(NPIX / BP, QN / BQ, NB), NT>>>(mf, out);
}

// round 4
// speedup vs baseline: 3.5720x; 3.5720x over previous
#include <cuda_runtime.h>
#include <cuda_bf16.h>
#include <cstdint>

#define HID  256
#define QN   200
#define NPIX (256 * 256)
#define NB   4

#define MROWS   13        // ceil(200/16) query row-tiles of 16
#define KSTEPS  16        // 256 / 16
#define PTILE   64        // pixels per GEMM CTA
#define BSTRIDE 132       // smem row stride in u32 (k-pairs), read-conflict-free

// ---------------------------------------------------------------------------
// Device scratch (allocation-free)
// ---------------------------------------------------------------------------
__device__ float g_me[NB * QN * HID];                       // mask_embed fp32
__device__ uint4 g_AH[NB * MROWS * KSTEPS * 32];            // A hi fragments
__device__ uint4 g_AL[NB * MROWS * KSTEPS * 32];            // A lo fragments

// ---------------------------------------------------------------------------
// mma.sync m16n8k16 bf16 (baseline PTX, valid on sm_100)
// ---------------------------------------------------------------------------
__device__ __forceinline__ void mma_bf16(float* d, uint4 a, uint32_t b0, uint32_t b1) {
    asm volatile(
        "mma.sync.aligned.m16n8k16.row.col.f32.bf16.bf16.f32 "
        "{%0,%1,%2,%3}, {%4,%5,%6,%7}, {%8,%9}, {%0,%1,%2,%3};"
        : "+f"(d[0]), "+f"(d[1]), "+f"(d[2]), "+f"(d[3])
        : "r"(a.x), "r"(a.y), "r"(a.z), "r"(a.w), "r"(b0), "r"(b1));
}

__device__ __forceinline__ uint32_t pack_bf16(float a, float b) {
    __nv_bfloat162 h = __floats2bfloat162_rn(a, b);
    return *reinterpret_cast<uint32_t*>(&h);
}

// ---------------------------------------------------------------------------
// Kernel 1: per-query MLP (unchanged; writes g_me fp32)
// ---------------------------------------------------------------------------
__global__ __launch_bounds__(256) void mlp_kernel(
    const float* __restrict__ queries,
    const float* __restrict__ w1, const float* __restrict__ b1,
    const float* __restrict__ w2, const float* __restrict__ b2)
{
    const int b  = blockIdx.y;
    const int q0 = blockIdx.x * 8;
    const int tid = threadIdx.x;

    __shared__ float qs[8][HID];
    __shared__ float hs[8][HID];

    const float* qbase = queries + (size_t)(b * QN + q0) * HID;
    for (int i = tid; i < 8 * HID; i += 256)
        qs[i >> 8][i & 255] = qbase[i];
    __syncthreads();

    {
        const int d = tid;
        float acc[8] = {0.f,0.f,0.f,0.f,0.f,0.f,0.f,0.f};
        const float4* wr = reinterpret_cast<const float4*>(w1 + (size_t)d * HID);
        #pragma unroll 8
        for (int c4 = 0; c4 < HID / 4; c4++) {
            float4 w = wr[c4];
            #pragma unroll
            for (int j = 0; j < 8; j++) {
                acc[j] = fmaf(qs[j][4*c4+0], w.x, acc[j]);
                acc[j] = fmaf(qs[j][4*c4+1], w.y, acc[j]);
                acc[j] = fmaf(qs[j][4*c4+2], w.z, acc[j]);
                acc[j] = fmaf(qs[j][4*c4+3], w.w, acc[j]);
            }
        }
        const float bb = b1[d];
        #pragma unroll
        for (int j = 0; j < 8; j++) {
            float v = acc[j] + bb;
            hs[j][d] = v > 0.f ? v : 0.f;
        }
    }
    __syncthreads();
    {
        const int c = tid;
        float acc[8] = {0.f,0.f,0.f,0.f,0.f,0.f,0.f,0.f};
        const float4* wr = reinterpret_cast<const float4*>(w2 + (size_t)c * HID);
        #pragma unroll 8
        for (int d4 = 0; d4 < HID / 4; d4++) {
            float4 w = wr[d4];
            #pragma unroll
            for (int j = 0; j < 8; j++) {
                acc[j] = fmaf(hs[j][4*d4+0], w.x, acc[j]);
                acc[j] = fmaf(hs[j][4*d4+1], w.y, acc[j]);
                acc[j] = fmaf(hs[j][4*d4+2], w.z, acc[j]);
                acc[j] = fmaf(hs[j][4*d4+3], w.w, acc[j]);
            }
        }
        const float bb = b2[c];
        #pragma unroll
        for (int j = 0; j < 8; j++)
            g_me[(size_t)(b * QN + q0 + j) * HID + c] = acc[j] + bb;
    }
}

// ---------------------------------------------------------------------------
// Kernel 2: pack mask_embed into per-lane A fragments (hi/lo bf16 split).
// grid = NB*MROWS blocks, 512 threads (warp ws = kstep).
// A frag (m16n8k16): lane t (g=t/4, i=t%4) holds rows {mr*16+g, +8},
// cols {ks*16+2i, +1, +8, +9}.
// ---------------------------------------------------------------------------
__global__ __launch_bounds__(512) void pack_kernel()
{
    const int blk = blockIdx.x;              // b*MROWS + mr
    const int b   = blk / MROWS;
    const int mr  = blk % MROWS;
    const int ks  = threadIdx.x >> 5;        // 0..15
    const int lane = threadIdx.x & 31;
    const int g = lane >> 2, i4 = lane & 3;

    const int r0 = mr * 16 + g;
    const int r1 = r0 + 8;
    const int c0 = ks * 16 + i4 * 2;

    float v[2][4];   // [row][col: c0, c0+1, c0+8, c0+9]
    #pragma unroll
    for (int rr = 0; rr < 2; rr++) {
        const int r = rr ? r1 : r0;
        #pragma unroll
        for (int cc = 0; cc < 4; cc++) {
            const int c = c0 + (cc >> 1) * 8 + (cc & 1);
            v[rr][cc] = (r < QN) ? g_me[(size_t)(b * QN + r) * HID + c] : 0.f;
        }
    }

    uint4 ah, al;
    float h0, h1;
    // a0: (r0, c0/c0+1)
    h0 = __bfloat162float(__float2bfloat16_rn(v[0][0]));
    h1 = __bfloat162float(__float2bfloat16_rn(v[0][1]));
    ah.x = pack_bf16(h0, h1);  al.x = pack_bf16(v[0][0]-h0, v[0][1]-h1);
    // a1: (r1, c0/c0+1)
    h0 = __bfloat162float(__float2bfloat16_rn(v[1][0]));
    h1 = __bfloat162float(__float2bfloat16_rn(v[1][1]));
    ah.y = pack_bf16(h0, h1);  al.y = pack_bf16(v[1][0]-h0, v[1][1]-h1);
    // a2: (r0, c0+8/+9)
    h0 = __bfloat162float(__float2bfloat16_rn(v[0][2]));
    h1 = __bfloat162float(__float2bfloat16_rn(v[0][3]));
    ah.z = pack_bf16(h0, h1);  al.z = pack_bf16(v[0][2]-h0, v[0][3]-h1);
    // a3: (r1, c0+8/+9)
    h0 = __bfloat162float(__float2bfloat16_rn(v[1][2]));
    h1 = __bfloat162float(__float2bfloat16_rn(v[1][3]));
    ah.w = pack_bf16(h0, h1);  al.w = pack_bf16(v[1][2]-h0, v[1][3]-h1);

    const size_t idx = ((size_t)(b * MROWS + mr) * KSTEPS + ks) * 32 + lane;
    g_AH[idx] = ah;
    g_AL[idx] = al;
}

// ---------------------------------------------------------------------------
// Kernel 3: mma.sync GEMM.  out[b,q,p] = sum_c me[b,q,c] * mf[b,c,p]
// CTA = 64-pixel stripe x all 208 padded query rows (mf read exactly once).
// B tile converted fp32 -> bf16 hi/lo into smem [pixel][kpair], stride 132.
// D = Ah*Bh + Al*Bh + Ah*Bl, fp32 accum in registers.
// Warp w owns mrows {w, w+8}.
// ---------------------------------------------------------------------------
__global__ __launch_bounds__(256) void gemm_kernel(
    const float* __restrict__ mf, float* __restrict__ out)
{
    extern __shared__ uint32_t sB[];               // sBH[64*132] ++ sBL[64*132]
    uint32_t* sBH = sB;
    uint32_t* sBL = sB + PTILE * BSTRIDE;

    const int tid  = threadIdx.x;
    const int lane = tid & 31;
    const int w    = tid >> 5;
    const int g    = lane >> 2, i4 = lane & 3;

    const int p0 = blockIdx.x * PTILE;
    const int b  = blockIdx.y;

    const float* mfb  = mf  + (size_t)b * HID * NPIX;
    float*       outb = out + (size_t)b * QN  * NPIX;

    // ---- load + convert B tile: 64 pixels x 256 channels ----
    // item = (cpair 0..127, p4 0..15): read mf rows 2cp, 2cp+1, 4 pixels each.
    #pragma unroll
    for (int it = 0; it < 8; it++) {
        const int idx = it * 256 + tid;
        const int cp  = idx >> 4;
        const int p4  = idx & 15;
        const float* r0 = mfb + (size_t)(2 * cp)     * NPIX + p0 + p4 * 4;
        const float* r1 = mfb + (size_t)(2 * cp + 1) * NPIX + p0 + p4 * 4;
        float4 v0 = *reinterpret_cast<const float4*>(r0);
        float4 v1 = *reinterpret_cast<const float4*>(r1);
        const float a0[4] = {v0.x, v0.y, v0.z, v0.w};
        const float a1[4] = {v1.x, v1.y, v1.z, v1.w};
        #pragma unroll
        for (int s = 0; s < 4; s++) {
            const int j = (s + p4) & 3;            // stagger -> fewer bank conflicts
            float h0 = __bfloat162float(__float2bfloat16_rn(a0[j]));
            float h1 = __bfloat162float(__float2bfloat16_rn(a1[j]));
            const uint32_t off = (uint32_t)(p4 * 4 + j) * BSTRIDE + cp;
            sBH[off] = pack_bf16(h0, h1);
            sBL[off] = pack_bf16(a0[j] - h0, a1[j] - h1);
        }
    }
    __syncthreads();

    // ---- compute ----
    const int mr0 = w;
    const int mr1 = w + 8;
    const bool has1 = (mr1 < MROWS);

    float acc0[8][4];
    float acc1[8][4];
    #pragma unroll
    for (int n = 0; n < 8; n++)
        #pragma unroll
        for (int x = 0; x < 4; x++) { acc0[n][x] = 0.f; acc1[n][x] = 0.f; }

    const uint4* pAH0 = g_AH + ((size_t)(b * MROWS + mr0) * KSTEPS) * 32 + lane;
    const uint4* pAL0 = g_AL + ((size_t)(b * MROWS + mr0) * KSTEPS) * 32 + lane;
    const uint4* pAH1 = g_AH + ((size_t)(b * MROWS + (has1 ? mr1 : mr0)) * KSTEPS) * 32 + lane;
    const uint4* pAL1 = g_AL + ((size_t)(b * MROWS + (has1 ? mr1 : mr0)) * KSTEPS) * 32 + lane;

    #pragma unroll 4
    for (int ks = 0; ks < KSTEPS; ks++) {
        const uint4 ah0 = pAH0[ks * 32];
        const uint4 al0 = pAL0[ks * 32];
        uint4 ah1, al1;
        if (has1) { ah1 = pAH1[ks * 32]; al1 = pAL1[ks * 32]; }

        const uint32_t cb = (uint32_t)(ks * 8 + i4);
        #pragma unroll
        for (int nc = 0; nc < 8; nc++) {
            const uint32_t rb = (uint32_t)(nc * 8 + g) * BSTRIDE;
            const uint32_t b0h = sBH[rb + cb];
            const uint32_t b1h = sBH[rb + cb + 4];
            const uint32_t b0l = sBL[rb + cb];
            const uint32_t b1l = sBL[rb + cb + 4];
            mma_bf16(acc0[nc], ah0, b0h, b1h);
            mma_bf16(acc0[nc], al0, b0h, b1h);
            mma_bf16(acc0[nc], ah0, b0l, b1l);
            if (has1) {
                mma_bf16(acc1[nc], ah1, b0h, b1h);
                mma_bf16(acc1[nc], al1, b0h, b1h);
                mma_bf16(acc1[nc], ah1, b0l, b1l);
            }
        }
    }

    // ---- epilogue: D frag (16x8) rows = queries, cols = pixel pairs ----
    {
        const int q = mr0 * 16 + g;                         // always < 200
        float* o = outb + (size_t)q * NPIX + p0 + i4 * 2;
        #pragma unroll
        for (int nc = 0; nc < 8; nc++)
            *reinterpret_cast<float2*>(o + nc * 8) = make_float2(acc0[nc][0], acc0[nc][1]);
        const int q2 = q + 8;
        if (q2 < QN) {
            float* o2 = outb + (size_t)q2 * NPIX + p0 + i4 * 2;
            #pragma unroll
            for (int nc = 0; nc < 8; nc++)
                *reinterpret_cast<float2*>(o2 + nc * 8) = make_float2(acc0[nc][2], acc0[nc][3]);
        }
    }
    if (has1) {
        const int q = mr1 * 16 + g;
        if (q < QN) {
            float* o = outb + (size_t)q * NPIX + p0 + i4 * 2;
            #pragma unroll
            for (int nc = 0; nc < 8; nc++)
                *reinterpret_cast<float2*>(o + nc * 8) = make_float2(acc1[nc][0], acc1[nc][1]);
        }
        const int q2 = q + 8;
        if (q2 < QN) {
            float* o2 = outb + (size_t)q2 * NPIX + p0 + i4 * 2;
            #pragma unroll
            for (int nc = 0; nc < 8; nc++)
                *reinterpret_cast<float2*>(o2 + nc * 8) = make_float2(acc1[nc][2], acc1[nc][3]);
        }
    }
}

// ---------------------------------------------------------------------------
extern "C" void kernel_launch(void* const* d_in, const int* in_sizes, int n_in,
                              void* d_out, int out_size)
{
    const float* queries = (const float*)d_in[0];  // (4, 200, 256)
    const float* mf      = (const float*)d_in[1];  // (4, 256, 256, 256)
    const float* w1      = (const float*)d_in[2];
    const float* b1      = (const float*)d_in[3];
    const float* w2      = (const float*)d_in[4];
    const float* b2      = (const float*)d_in[5];
    float* out = (float*)d_out;                    // (4, 200, 256, 256)

    const int smem = 2 * PTILE * BSTRIDE * (int)sizeof(uint32_t);   // 67584 B
    cudaFuncSetAttribute(gemm_kernel, cudaFuncAttributeMaxDynamicSharedMemorySize, smem);

    mlp_kernel<<<dim3(QN / 8, NB), 256>>>(queries, w1, b1, w2, b2);
    pack_kernel<<<NB * MROWS, 512>>>();
    gemm_kernel<<<dim3(NPIX / PTILE, NB), 256, smem>>>(mf, out);
}

// round 6
// speedup vs baseline: 4.3410x; 1.2153x over previous
#include <cuda_runtime.h>
#include <cuda_fp16.h>
#include <cstdint>

#define HID  256
#define QN   200
#define NPIX (256 * 256)
#define NB   4

#define MROWS   13        // ceil(200/16) query row-tiles of 16
#define KSTEPS  16        // 256 / 16
#define PTILE   64        // pixels per GEMM CTA
#define BSTRIDE 132       // smem row stride in u32 (k-pairs), read-conflict-free

// ---------------------------------------------------------------------------
// Device scratch (allocation-free)
// ---------------------------------------------------------------------------
__device__ float g_me[NB * QN * HID];                       // mask_embed fp32
__device__ uint4 g_AH[NB * MROWS * KSTEPS * 32];            // A hi fragments (fp16)
__device__ uint4 g_AL[NB * MROWS * KSTEPS * 32];            // A lo fragments (fp16)

// ---------------------------------------------------------------------------
// mma.sync m16n8k16 fp16 in / fp32 accum (baseline PTX, valid on sm_100)
// ---------------------------------------------------------------------------
__device__ __forceinline__ void mma_f16(float* d, uint4 a, uint32_t b0, uint32_t b1) {
    asm volatile(
        "mma.sync.aligned.m16n8k16.row.col.f32.f16.f16.f32 "
        "{%0,%1,%2,%3}, {%4,%5,%6,%7}, {%8,%9}, {%0,%1,%2,%3};"
        : "+f"(d[0]), "+f"(d[1]), "+f"(d[2]), "+f"(d[3])
        : "r"(a.x), "r"(a.y), "r"(a.z), "r"(a.w), "r"(b0), "r"(b1));
}

__device__ __forceinline__ uint32_t pack_f16(float a, float b) {
    __half2 h = __floats2half2_rn(a, b);
    return *reinterpret_cast<uint32_t*>(&h);
}

// ---------------------------------------------------------------------------
// Kernel 1: per-query MLP. 4 queries/block -> grid (50, NB) covers all SMs.
// ---------------------------------------------------------------------------
__global__ __launch_bounds__(256) void mlp_kernel(
    const float* __restrict__ queries,
    const float* __restrict__ w1, const float* __restrict__ b1,
    const float* __restrict__ w2, const float* __restrict__ b2)
{
    const int b  = blockIdx.y;
    const int q0 = blockIdx.x * 4;
    const int tid = threadIdx.x;

    __shared__ float qs[4][HID];
    __shared__ float hs[4][HID];

    const float* qbase = queries + (size_t)(b * QN + q0) * HID;
    for (int i = tid; i < 4 * HID; i += 256)
        qs[i >> 8][i & 255] = qbase[i];
    __syncthreads();

    {
        const int d = tid;
        float acc[4] = {0.f, 0.f, 0.f, 0.f};
        const float4* wr = reinterpret_cast<const float4*>(w1 + (size_t)d * HID);
        #pragma unroll 16
        for (int c4 = 0; c4 < HID / 4; c4++) {
            float4 w = wr[c4];
            #pragma unroll
            for (int j = 0; j < 4; j++) {
                acc[j] = fmaf(qs[j][4*c4+0], w.x, acc[j]);
                acc[j] = fmaf(qs[j][4*c4+1], w.y, acc[j]);
                acc[j] = fmaf(qs[j][4*c4+2], w.z, acc[j]);
                acc[j] = fmaf(qs[j][4*c4+3], w.w, acc[j]);
            }
        }
        const float bb = b1[d];
        #pragma unroll
        for (int j = 0; j < 4; j++) {
            float v = acc[j] + bb;
            hs[j][d] = v > 0.f ? v : 0.f;
        }
    }
    __syncthreads();
    {
        const int c = tid;
        float acc[4] = {0.f, 0.f, 0.f, 0.f};
        const float4* wr = reinterpret_cast<const float4*>(w2 + (size_t)c * HID);
        #pragma unroll 16
        for (int d4 = 0; d4 < HID / 4; d4++) {
            float4 w = wr[d4];
            #pragma unroll
            for (int j = 0; j < 4; j++) {
                acc[j] = fmaf(hs[j][4*d4+0], w.x, acc[j]);
                acc[j] = fmaf(hs[j][4*d4+1], w.y, acc[j]);
                acc[j] = fmaf(hs[j][4*d4+2], w.z, acc[j]);
                acc[j] = fmaf(hs[j][4*d4+3], w.w, acc[j]);
            }
        }
        const float bb = b2[c];
        #pragma unroll
        for (int j = 0; j < 4; j++)
            g_me[(size_t)(b * QN + q0 + j) * HID + c] = acc[j] + bb;
    }
}

// ---------------------------------------------------------------------------
// Kernel 2: pack mask_embed into per-lane A fragments (fp16 hi/lo split).
// A frag (m16n8k16): lane t (g=t/4, i=t%4) holds rows {mr*16+g, +8},
// cols {ks*16+2i, +1, +8, +9}.
// ---------------------------------------------------------------------------
__global__ __launch_bounds__(512) void pack_kernel()
{
    const int blk = blockIdx.x;              // b*MROWS + mr
    const int b   = blk / MROWS;
    const int mr  = blk % MROWS;
    const int ks  = threadIdx.x >> 5;        // 0..15
    const int lane = threadIdx.x & 31;
    const int g = lane >> 2, i4 = lane & 3;

    const int r0 = mr * 16 + g;
    const int r1 = r0 + 8;
    const int c0 = ks * 16 + i4 * 2;

    float v[2][4];   // [row][col: c0, c0+1, c0+8, c0+9]
    #pragma unroll
    for (int rr = 0; rr < 2; rr++) {
        const int r = rr ? r1 : r0;
        #pragma unroll
        for (int cc = 0; cc < 4; cc++) {
            const int c = c0 + (cc >> 1) * 8 + (cc & 1);
            v[rr][cc] = (r < QN) ? g_me[(size_t)(b * QN + r) * HID + c] : 0.f;
        }
    }

    uint4 ah, al;
    float h0, h1;
    h0 = __half2float(__float2half_rn(v[0][0]));
    h1 = __half2float(__float2half_rn(v[0][1]));
    ah.x = pack_f16(h0, h1);  al.x = pack_f16(v[0][0]-h0, v[0][1]-h1);
    h0 = __half2float(__float2half_rn(v[1][0]));
    h1 = __half2float(__float2half_rn(v[1][1]));
    ah.y = pack_f16(h0, h1);  al.y = pack_f16(v[1][0]-h0, v[1][1]-h1);
    h0 = __half2float(__float2half_rn(v[0][2]));
    h1 = __half2float(__float2half_rn(v[0][3]));
    ah.z = pack_f16(h0, h1);  al.z = pack_f16(v[0][2]-h0, v[0][3]-h1);
    h0 = __half2float(__float2half_rn(v[1][2]));
    h1 = __half2float(__float2half_rn(v[1][3]));
    ah.w = pack_f16(h0, h1);  al.w = pack_f16(v[1][2]-h0, v[1][3]-h1);

    const size_t idx = ((size_t)(b * MROWS + mr) * KSTEPS + ks) * 32 + lane;
    g_AH[idx] = ah;
    g_AL[idx] = al;
}

// ---------------------------------------------------------------------------
// Kernel 3: mma.sync GEMM.  out[b,q,p] = sum_c me[b,q,c] * mf[b,c,p]
// CTA = 64-pixel stripe x all 208 padded query rows (mf read exactly once).
// B rounded once to fp16 into smem [pixel][kpair], stride 132.
// D = (Ah + Al) * B  -> 2 MMA products (error ~2^-11 elementwise, O(1) amp).
// Heavy/light warp roles rotated by blockIdx.x for SMSP balance.
// ---------------------------------------------------------------------------
__global__ __launch_bounds__(256) void gemm_kernel(
    const float* __restrict__ mf, float* __restrict__ out)
{
    extern __shared__ uint32_t sB[];               // [64 pixels][BSTRIDE kpairs]

    const int tid  = threadIdx.x;
    const int lane = tid & 31;
    const int w    = tid >> 5;
    const int g    = lane >> 2, i4 = lane & 3;

    const int p0 = blockIdx.x * PTILE;
    const int b  = blockIdx.y;

    const float* mfb  = mf  + (size_t)b * HID * NPIX;
    float*       outb = out + (size_t)b * QN  * NPIX;

    // ---- load + convert B tile: 64 pixels x 256 channels, fp32 -> fp16 ----
    #pragma unroll
    for (int it = 0; it < 8; it++) {
        const int idx = it * 256 + tid;
        const int cp  = idx >> 4;
        const int p4  = idx & 15;
        const float* r0 = mfb + (size_t)(2 * cp)     * NPIX + p0 + p4 * 4;
        const float* r1 = mfb + (size_t)(2 * cp + 1) * NPIX + p0 + p4 * 4;
        float4 v0 = *reinterpret_cast<const float4*>(r0);
        float4 v1 = *reinterpret_cast<const float4*>(r1);
        const float a0[4] = {v0.x, v0.y, v0.z, v0.w};
        const float a1[4] = {v1.x, v1.y, v1.z, v1.w};
        #pragma unroll
        for (int s = 0; s < 4; s++) {
            const int j = (s + p4) & 3;            // stagger -> fewer store conflicts
            sB[(uint32_t)(p4 * 4 + j) * BSTRIDE + cp] = pack_f16(a0[j], a1[j]);
        }
    }
    __syncthreads();

    // ---- compute: warp role rotated by blockIdx.x for SMSP load balance ----
    const int wp  = (w + (int)(blockIdx.x & 7)) & 7;
    const int mr0 = wp;
    const int mr1 = wp + 8;
    const bool has1 = (mr1 < MROWS);

    float acc0[8][4];
    float acc1[8][4];
    #pragma unroll
    for (int n = 0; n < 8; n++)
        #pragma unroll
        for (int x = 0; x < 4; x++) { acc0[n][x] = 0.f; acc1[n][x] = 0.f; }

    const uint4* pAH0 = g_AH + ((size_t)(b * MROWS + mr0) * KSTEPS) * 32 + lane;
    const uint4* pAL0 = g_AL + ((size_t)(b * MROWS + mr0) * KSTEPS) * 32 + lane;
    const uint4* pAH1 = g_AH + ((size_t)(b * MROWS + (has1 ? mr1 : mr0)) * KSTEPS) * 32 + lane;
    const uint4* pAL1 = g_AL + ((size_t)(b * MROWS + (has1 ? mr1 : mr0)) * KSTEPS) * 32 + lane;

    #pragma unroll 4
    for (int ks = 0; ks < KSTEPS; ks++) {
        const uint4 ah0 = pAH0[ks * 32];
        const uint4 al0 = pAL0[ks * 32];
        uint4 ah1, al1;
        if (has1) { ah1 = pAH1[ks * 32]; al1 = pAL1[ks * 32]; }

        const uint32_t cb = (uint32_t)(ks * 8 + i4);
        #pragma unroll
        for (int nc = 0; nc < 8; nc++) {
            const uint32_t rb = (uint32_t)(nc * 8 + g) * BSTRIDE;
            const uint32_t b0 = sB[rb + cb];
            const uint32_t b1 = sB[rb + cb + 4];
            mma_f16(acc0[nc], ah0, b0, b1);
            mma_f16(acc0[nc], al0, b0, b1);
            if (has1) {
                mma_f16(acc1[nc], ah1, b0, b1);
                mma_f16(acc1[nc], al1, b0, b1);
            }
        }
    }

    // ---- epilogue: D frag (16x8) rows = queries, cols = pixel pairs ----
    {
        const int q = mr0 * 16 + g;                         // always < 200
        float* o = outb + (size_t)q * NPIX + p0 + i4 * 2;
        #pragma unroll
        for (int nc = 0; nc < 8; nc++)
            *reinterpret_cast<float2*>(o + nc * 8) = make_float2(acc0[nc][0], acc0[nc][1]);
        const int q2 = q + 8;
        if (q2 < QN) {
            float* o2 = outb + (size_t)q2 * NPIX + p0 + i4 * 2;
            #pragma unroll
            for (int nc = 0; nc < 8; nc++)
                *reinterpret_cast<float2*>(o2 + nc * 8) = make_float2(acc0[nc][2], acc0[nc][3]);
        }
    }
    if (has1) {
        const int q = mr1 * 16 + g;
        if (q < QN) {
            float* o = outb + (size_t)q * NPIX + p0 + i4 * 2;
            #pragma unroll
            for (int nc = 0; nc < 8; nc++)
                *reinterpret_cast<float2*>(o + nc * 8) = make_float2(acc1[nc][0], acc1[nc][1]);
        }
        const int q2 = q + 8;
        if (q2 < QN) {
            float* o2 = outb + (size_t)q2 * NPIX + p0 + i4 * 2;
            #pragma unroll
            for (int nc = 0; nc < 8; nc++)
                *reinterpret_cast<float2*>(o2 + nc * 8) = make_float2(acc1[nc][2], acc1[nc][3]);
        }
    }
}

// ---------------------------------------------------------------------------
extern "C" void kernel_launch(void* const* d_in, const int* in_sizes, int n_in,
                              void* d_out, int out_size)
{
    const float* queries = (const float*)d_in[0];  // (4, 200, 256)
    const float* mf      = (const float*)d_in[1];  // (4, 256, 256, 256)
    const float* w1      = (const float*)d_in[2];
    const float* b1      = (const float*)d_in[3];
    const float* w2      = (const float*)d_in[4];
    const float* b2      = (const float*)d_in[5];
    float* out = (float*)d_out;                    // (4, 200, 256, 256)

    const int smem = PTILE * BSTRIDE * (int)sizeof(uint32_t);   // 33792 B
    cudaFuncSetAttribute(gemm_kernel, cudaFuncAttributeMaxDynamicSharedMemorySize, smem);

    mlp_kernel<<<dim3(QN / 4, NB), 256>>>(queries, w1, b1, w2, b2);
    pack_kernel<<<NB * MROWS, 512>>>();
    gemm_kernel<<<dim3(NPIX / PTILE, NB), 256, smem>>>(mf, out);
}

// round 7
// speedup vs baseline: 6.4553x; 1.4871x over previous
#include <cuda_runtime.h>
#include <cuda_fp16.h>
#include <cstdint>

#define HID  256
#define QN   200
#define NPIX (256 * 256)
#define NB   4
#define NROW (NB * QN)    // 800 merged (b,q) rows

#define MROWS   13        // ceil(200/16) query row-tiles of 16
#define KSTEPS  16        // 256 / 16
#define PTILE   64        // pixels per GEMM CTA
#define BSTRIDE 132       // smem row stride in u32 (k-pairs), read-conflict-free
#define NWARP   13        // one warp per m-row tile
#define GTHREADS (NWARP * 32)

// ---------------------------------------------------------------------------
// Device scratch (allocation-free)
// ---------------------------------------------------------------------------
__device__ float g_h [NROW * HID];                          // hidden fp32
__device__ float g_me[NROW * HID];                          // mask_embed fp32
__device__ uint4 g_AH[NB * MROWS * KSTEPS * 32];            // A fragments (fp16)

// ---------------------------------------------------------------------------
// mma.sync m16n8k16 fp16 in / fp32 accum (baseline PTX, valid on sm_100)
// ---------------------------------------------------------------------------
__device__ __forceinline__ void mma_f16(float* d, uint4 a, uint32_t b0, uint32_t b1) {
    asm volatile(
        "mma.sync.aligned.m16n8k16.row.col.f32.f16.f16.f32 "
        "{%0,%1,%2,%3}, {%4,%5,%6,%7}, {%8,%9}, {%0,%1,%2,%3};"
        : "+f"(d[0]), "+f"(d[1]), "+f"(d[2]), "+f"(d[3])
        : "r"(a.x), "r"(a.y), "r"(a.z), "r"(a.w), "r"(b0), "r"(b1));
}

__device__ __forceinline__ uint32_t pack_f16(float a, float b) {
    __half2 h = __floats2half2_rn(a, b);
    return *reinterpret_cast<uint32_t*>(&h);
}

// ---------------------------------------------------------------------------
// MLP layer kernel: C[r, n] = act( sum_k A[r,k] * W[n,k] + bias[n] )
// 32x32 tile, 128 threads, coalesced smem staging (fixes the L1tex
// wavefront explosion of the per-thread-w-row version).
// grid = (NROW/32 = 25, HID/32 = 8)
// ---------------------------------------------------------------------------
template<bool RELU>
__global__ __launch_bounds__(128) void layer_kernel(
    const float* __restrict__ A, const float* __restrict__ W,
    const float* __restrict__ bias, float* __restrict__ C)
{
    __shared__ float sA[16][32];   // [k][row]
    __shared__ float sW[16][32];   // [k][col]

    const int tid = threadIdx.x;
    const int r0 = blockIdx.x * 32;
    const int n0 = blockIdx.y * 32;
    const int tr = tid & 7;        // row group: 4 rows
    const int tc = tid >> 3;       // col group: 2 cols (0..15)
    const int lrow = tid >> 2;     // 0..31: load row
    const int lj   = (tid & 3) * 4;

    float acc[4][2] = {};

    for (int kc = 0; kc < HID; kc += 16) {
        __syncthreads();
        // coalesced loads: 4 consecutive threads read 64B of one row
        float4 va = *reinterpret_cast<const float4*>(A + (size_t)(r0 + lrow) * HID + kc + lj);
        sA[lj+0][lrow] = va.x; sA[lj+1][lrow] = va.y;
        sA[lj+2][lrow] = va.z; sA[lj+3][lrow] = va.w;
        float4 vw = *reinterpret_cast<const float4*>(W + (size_t)(n0 + lrow) * HID + kc + lj);
        sW[lj+0][lrow] = vw.x; sW[lj+1][lrow] = vw.y;
        sW[lj+2][lrow] = vw.z; sW[lj+3][lrow] = vw.w;
        __syncthreads();

        #pragma unroll
        for (int k = 0; k < 16; k++) {
            float4 a = *reinterpret_cast<const float4*>(&sA[k][tr * 4]);
            float2 w = *reinterpret_cast<const float2*>(&sW[k][tc * 2]);
            acc[0][0] = fmaf(a.x, w.x, acc[0][0]); acc[0][1] = fmaf(a.x, w.y, acc[0][1]);
            acc[1][0] = fmaf(a.y, w.x, acc[1][0]); acc[1][1] = fmaf(a.y, w.y, acc[1][1]);
            acc[2][0] = fmaf(a.z, w.x, acc[2][0]); acc[2][1] = fmaf(a.z, w.y, acc[2][1]);
            acc[3][0] = fmaf(a.w, w.x, acc[3][0]); acc[3][1] = fmaf(a.w, w.y, acc[3][1]);
        }
    }

    const float b0 = bias[n0 + tc * 2];
    const float b1 = bias[n0 + tc * 2 + 1];
    #pragma unroll
    for (int r = 0; r < 4; r++) {
        float v0 = acc[r][0] + b0;
        float v1 = acc[r][1] + b1;
        if (RELU) { v0 = v0 > 0.f ? v0 : 0.f; v1 = v1 > 0.f ? v1 : 0.f; }
        *reinterpret_cast<float2*>(C + (size_t)(r0 + tr * 4 + r) * HID + n0 + tc * 2)
            = make_float2(v0, v1);
    }
}

// ---------------------------------------------------------------------------
// Pack mask_embed into per-lane A fragments (single fp16 rounding).
// A frag (m16n8k16): lane t (g=t/4, i=t%4) holds rows {mr*16+g, +8},
// cols {ks*16+2i, +1, +8, +9}.
// ---------------------------------------------------------------------------
__global__ __launch_bounds__(512) void pack_kernel()
{
    const int blk = blockIdx.x;              // b*MROWS + mr
    const int b   = blk / MROWS;
    const int mr  = blk % MROWS;
    const int ks  = threadIdx.x >> 5;        // 0..15
    const int lane = threadIdx.x & 31;
    const int g = lane >> 2, i4 = lane & 3;

    const int r0 = mr * 16 + g;
    const int r1 = r0 + 8;
    const int c0 = ks * 16 + i4 * 2;

    float v[2][4];
    #pragma unroll
    for (int rr = 0; rr < 2; rr++) {
        const int r = rr ? r1 : r0;
        #pragma unroll
        for (int cc = 0; cc < 4; cc++) {
            const int c = c0 + (cc >> 1) * 8 + (cc & 1);
            v[rr][cc] = (r < QN) ? g_me[(size_t)(b * QN + r) * HID + c] : 0.f;
        }
    }

    uint4 ah;
    ah.x = pack_f16(v[0][0], v[0][1]);
    ah.y = pack_f16(v[1][0], v[1][1]);
    ah.z = pack_f16(v[0][2], v[0][3]);
    ah.w = pack_f16(v[1][2], v[1][3]);

    g_AH[((size_t)(b * MROWS + mr) * KSTEPS + ks) * 32 + lane] = ah;
}

// ---------------------------------------------------------------------------
// GEMM: out[b,q,p] = sum_c me[b,q,c] * mf[b,c,p]
// CTA = 64-pixel stripe x all 208 padded query rows (mf read exactly once).
// 13 warps, one m-row tile each (perfect MMA balance), rotated by blockIdx.x.
// B rounded once to fp16 into smem [pixel][kpair], stride 132.
// Single MMA product: A and B each fp16-rounded (error ~2^-11, O(1) amp).
// ---------------------------------------------------------------------------
__global__ __launch_bounds__(GTHREADS) void gemm_kernel(
    const float* __restrict__ mf, float* __restrict__ out)
{
    extern __shared__ uint32_t sB[];               // [64 pixels][BSTRIDE kpairs]

    const int tid  = threadIdx.x;
    const int lane = tid & 31;
    const int w    = tid >> 5;
    const int g    = lane >> 2, i4 = lane & 3;

    const int p0 = blockIdx.x * PTILE;
    const int b  = blockIdx.y;

    const float* mfb  = mf  + (size_t)b * HID * NPIX;
    float*       outb = out + (size_t)b * QN  * NPIX;

    // ---- load + convert B tile: 64 pixels x 256 channels, fp32 -> fp16 ----
    for (int idx = tid; idx < 128 * 16; idx += GTHREADS) {
        const int cp  = idx >> 4;
        const int p4  = idx & 15;
        const float* r0 = mfb + (size_t)(2 * cp)     * NPIX + p0 + p4 * 4;
        const float* r1 = mfb + (size_t)(2 * cp + 1) * NPIX + p0 + p4 * 4;
        float4 v0 = *reinterpret_cast<const float4*>(r0);
        float4 v1 = *reinterpret_cast<const float4*>(r1);
        const float a0[4] = {v0.x, v0.y, v0.z, v0.w};
        const float a1[4] = {v1.x, v1.y, v1.z, v1.w};
        #pragma unroll
        for (int s = 0; s < 4; s++) {
            const int j = (s + p4) & 3;            // stagger -> fewer store conflicts
            sB[(uint32_t)(p4 * 4 + j) * BSTRIDE + cp] = pack_f16(a0[j], a1[j]);
        }
    }
    __syncthreads();

    // ---- compute: warp wp owns m-row tile wp; rotate for balance ----
    const int mr = (w + (int)blockIdx.x) % NWARP;

    float acc[8][4];
    #pragma unroll
    for (int n = 0; n < 8; n++)
        #pragma unroll
        for (int x = 0; x < 4; x++) acc[n][x] = 0.f;

    const uint4* pAH = g_AH + ((size_t)(b * MROWS + mr) * KSTEPS) * 32 + lane;

    #pragma unroll 4
    for (int ks = 0; ks < KSTEPS; ks++) {
        const uint4 ah = pAH[ks * 32];
        const uint32_t cb = (uint32_t)(ks * 8 + i4);
        #pragma unroll
        for (int nc = 0; nc < 8; nc++) {
            const uint32_t rb = (uint32_t)(nc * 8 + g) * BSTRIDE;
            mma_f16(acc[nc], ah, sB[rb + cb], sB[rb + cb + 4]);
        }
    }

    // ---- epilogue: D frag (16x8) rows = queries, cols = pixel pairs ----
    {
        const int q = mr * 16 + g;
        if (q < QN) {
            float* o = outb + (size_t)q * NPIX + p0 + i4 * 2;
            #pragma unroll
            for (int nc = 0; nc < 8; nc++)
                *reinterpret_cast<float2*>(o + nc * 8) = make_float2(acc[nc][0], acc[nc][1]);
        }
        const int q2 = q + 8;
        if (q2 < QN) {
            float* o2 = outb + (size_t)q2 * NPIX + p0 + i4 * 2;
            #pragma unroll
            for (int nc = 0; nc < 8; nc++)
                *reinterpret_cast<float2*>(o2 + nc * 8) = make_float2(acc[nc][2], acc[nc][3]);
        }
    }
}

// ---------------------------------------------------------------------------
extern "C" void kernel_launch(void* const* d_in, const int* in_sizes, int n_in,
                              void* d_out, int out_size)
{
    const float* queries = (const float*)d_in[0];  // (4, 200, 256)
    const float* mf      = (const float*)d_in[1];  // (4, 256, 256, 256)
    const float* w1      = (const float*)d_in[2];
    const float* b1      = (const float*)d_in[3];
    const float* w2      = (const float*)d_in[4];
    const float* b2      = (const float*)d_in[5];
    float* out = (float*)d_out;                    // (4, 200, 256, 256)

    float* hbuf;  cudaGetSymbolAddress((void**)&hbuf,  g_h);
    float* mebuf; cudaGetSymbolAddress((void**)&mebuf, g_me);

    const int smem = PTILE * BSTRIDE * (int)sizeof(uint32_t);   // 33792 B
    cudaFuncSetAttribute(gemm_kernel, cudaFuncAttributeMaxDynamicSharedMemorySize, smem);

    layer_kernel<true ><<<dim3(NROW / 32, HID / 32), 128>>>(queries, w1, b1, hbuf);
    layer_kernel<false><<<dim3(NROW / 32, HID / 32), 128>>>(hbuf,    w2, b2, mebuf);
    pack_kernel<<<NB * MROWS, 512>>>();
    gemm_kernel<<<dim3(NPIX / PTILE, NB), GTHREADS, smem>>>(mf, out);
}